// round 1
// baseline (speedup 1.0000x reference)
#include <cuda_runtime.h>
#include <cuda_bf16.h>
#include <math_constants.h>

// Problem constants
#define NQ      65536       // number of query rows (B*D*H*W)
#define DIMV    256         // embedding dim
#define KCODES  1024        // codebook size
#define SPAT    16384       // D*H*W
#define NTOT    16777216    // B*C*D*H*W = z_q element count
#define CSTRIDE 16384       // stride between channels in z

// ---------------- device scratch (no allocations allowed) ----------------
__device__ float g_heq2[KCODES];            // 0.5 * |e_k|^2
__device__ int   g_idx[NQ];                 // argmin index per row
__device__ int   g_cnt[KCODES];             // cluster counts
__device__ float g_esum[KCODES * DIMV];     // per-code embed sums
__device__ float g_invc[KCODES];            // 1 / cluster_size
__device__ float g_newembed[KCODES * DIMV]; // updated codebook
__device__ float g_loss;                    // loss accumulator

// ---------------- f32x2 helpers (Blackwell packed fp32) ----------------
__device__ __forceinline__ unsigned long long fma2(unsigned long long a,
                                                   unsigned long long b,
                                                   unsigned long long c) {
    unsigned long long d;
    asm("fma.rn.f32x2 %0, %1, %2, %3;" : "=l"(d) : "l"(a), "l"(b), "l"(c));
    return d;
}
__device__ __forceinline__ unsigned long long pk2(float x) {
    unsigned long long r;
    asm("mov.b64 %0, {%1, %1};" : "=l"(r) : "f"(x));
    return r;
}
__device__ __forceinline__ float2 up2(unsigned long long v) {
    float2 f;
    asm("mov.b64 {%0, %1}, %2;" : "=f"(f.x), "=f"(f.y) : "l"(v));
    return f;
}

// ---------------- kernel: zero scratch + compute 0.5|e|^2 ----------------
__global__ void k_prep(const float* __restrict__ embed) {
    int gtid = blockIdx.x * blockDim.x + threadIdx.x;   // grid covers 262144
    if (gtid < KCODES * DIMV) g_esum[gtid] = 0.0f;
    if (gtid < KCODES) g_cnt[gtid] = 0;
    if (gtid == 0) g_loss = 0.0f;

    int w = gtid >> 5;
    int lane = gtid & 31;
    if (w < KCODES) {
        float s = 0.0f;
        #pragma unroll
        for (int j = 0; j < 8; ++j) {
            float v = embed[w * DIMV + lane + 32 * j];
            s += v * v;
        }
        #pragma unroll
        for (int o = 16; o; o >>= 1) s += __shfl_xor_sync(0xFFFFFFFFu, s, o);
        if (lane == 0) g_heq2[w] = 0.5f * s;
    }
}

// ---------------- kernel: fused distance-GEMM + argmin + scatter ----------------
// block: 256 threads, 128 rows; z tile [256 dims][128 rows] resident in smem.
// codes processed in chunks of 64, dims in steps of 32, e-tile double-buffered.
#define ZS_PAD   130                        // row-dim pad (even, conflict-free)
#define ZS_ELEMS (DIMV * ZS_PAD)            // 33280 floats
#define ES_PITCH 33                         // u64 per (code) row
#define ES_ELEMS (64 * ES_PITCH)            // 2112 u64 per buffer

__global__ __launch_bounds__(256, 1) void k_argmin(const float* __restrict__ z,
                                                   const float* __restrict__ embed) {
    extern __shared__ char smraw[];
    float*              zs    = reinterpret_cast<float*>(smraw);                    // 133120 B
    unsigned long long* es2   = reinterpret_cast<unsigned long long*>(smraw + 133120); // 33792 B
    float*              heq2s = reinterpret_cast<float*>(smraw + 166912);           // 4096 B
    float*              rbest = reinterpret_cast<float*>(smraw + 171008);           // 4096 B
    int*                ridx  = reinterpret_cast<int*>(smraw + 175104);             // 4096 B
    int*                sbi   = reinterpret_cast<int*>(smraw + 179200);             // 512 B

    const int t = threadIdx.x;
    const int lane = t & 31;
    const int warp = t >> 5;

    // ---- load z tile: zs[c][r] = z[b, c, s0+r], coalesced along rows ----
    const int n0 = blockIdx.x * 128;
    const int b  = n0 / SPAT;
    const int s0 = n0 % SPAT;
    const float* zbase = z + (size_t)b * (size_t)(DIMV * SPAT) + s0;
    #pragma unroll 4
    for (int i = 0; i < 128; ++i) {
        int id = t + 256 * i;           // 32768 elements
        int c = id >> 7;
        int r = id & 127;
        zs[c * ZS_PAD + r] = zbase[(size_t)c * CSTRIDE + r];
    }
    // ---- load 0.5|e|^2 table ----
    #pragma unroll
    for (int i = 0; i < 4; ++i) heq2s[t + 256 * i] = g_heq2[t + 256 * i];

    // ---- prefetch e-tile 0 (codes 0..63, dims 0..31) ----
    float pf[8];
    {
        #pragma unroll
        for (int i = 0; i < 8; ++i) {
            int id = t + 256 * i;       // 2048 entries
            int cj = id >> 5;
            int kk = id & 31;
            pf[i] = embed[cj * DIMV + kk];
        }
        #pragma unroll
        for (int i = 0; i < 8; ++i) {
            int id = t + 256 * i;
            int cj = id >> 5;
            int kk = id & 31;
            es2[cj * ES_PITCH + kk] = pk2(pf[i]);
        }
    }
    __syncthreads();

    unsigned long long acc[2][8];
    float best0 = -CUDART_INF_F, best1 = -CUDART_INF_F,
          best2 = -CUDART_INF_F, best3 = -CUDART_INF_F;
    int bi0 = 0, bi1 = 0, bi2 = 0, bi3 = 0;

    int buf = 0;
    for (int tau = 0; tau < 128; ++tau) {          // 16 code-chunks x 8 dim-steps
        const int kt = tau & 7;

        // prefetch next tile from global into regs (no sync needed)
        if (tau + 1 < 128) {
            int tn = tau + 1;
            int c0n = (tn >> 3) * 64;
            int ktn = tn & 7;
            #pragma unroll
            for (int i = 0; i < 8; ++i) {
                int id = t + 256 * i;
                int cj = id >> 5;
                int kk = id & 31;
                pf[i] = embed[(c0n + cj) * DIMV + ktn * 32 + kk];
            }
        }

        if (kt == 0) {
            #pragma unroll
            for (int p = 0; p < 2; ++p)
                #pragma unroll
                for (int j = 0; j < 8; ++j) acc[p][j] = 0ull;
        }

        // ---- main FMA loop: rows {2l,2l+1} and {64+2l,65+2l} x 8 codes ----
        const unsigned long long* eb = es2 + buf * ES_ELEMS + warp * 8 * ES_PITCH;
        #pragma unroll
        for (int kk = 0; kk < 32; ++kk) {
            const float* zr = zs + (kt * 32 + kk) * ZS_PAD;
            unsigned long long za = *reinterpret_cast<const unsigned long long*>(zr + 2 * lane);
            unsigned long long zb2 = *reinterpret_cast<const unsigned long long*>(zr + 64 + 2 * lane);
            #pragma unroll
            for (int j = 0; j < 8; ++j) {
                unsigned long long ev = eb[j * ES_PITCH + kk];
                acc[0][j] = fma2(za,  ev, acc[0][j]);
                acc[1][j] = fma2(zb2, ev, acc[1][j]);
            }
        }

        // ---- chunk epilogue: fold 0.5|e|^2, update running argmax of (z.e - h) ----
        if (kt == 7) {
            int cbase = (tau >> 3) * 64 + warp * 8;
            #pragma unroll
            for (int j = 0; j < 8; ++j) {
                float h = heq2s[cbase + j];
                float2 a = up2(acc[0][j]);
                float2 c2 = up2(acc[1][j]);
                int cc = cbase + j;
                float v0 = a.x - h, v1 = a.y - h, v2 = c2.x - h, v3 = c2.y - h;
                if (v0 > best0) { best0 = v0; bi0 = cc; }
                if (v1 > best1) { best1 = v1; bi1 = cc; }
                if (v2 > best2) { best2 = v2; bi2 = cc; }
                if (v3 > best3) { best3 = v3; bi3 = cc; }
            }
        }

        // store prefetched tile to the other buffer
        if (tau + 1 < 128) {
            unsigned long long* ebn = es2 + (buf ^ 1) * ES_ELEMS;
            #pragma unroll
            for (int i = 0; i < 8; ++i) {
                int id = t + 256 * i;
                int cj = id >> 5;
                int kk = id & 31;
                ebn[cj * ES_PITCH + kk] = pk2(pf[i]);
            }
        }
        __syncthreads();
        buf ^= 1;
    }

    // ---- cross-warp argmin reduction (tie -> smaller code index) ----
    rbest[warp * 128 + 2 * lane]      = best0; ridx[warp * 128 + 2 * lane]      = bi0;
    rbest[warp * 128 + 2 * lane + 1]  = best1; ridx[warp * 128 + 2 * lane + 1]  = bi1;
    rbest[warp * 128 + 64 + 2 * lane] = best2; ridx[warp * 128 + 64 + 2 * lane] = bi2;
    rbest[warp * 128 + 65 + 2 * lane] = best3; ridx[warp * 128 + 65 + 2 * lane] = bi3;
    __syncthreads();
    if (t < 128) {
        float bv = rbest[t];
        int   bi = ridx[t];
        #pragma unroll
        for (int w = 1; w < 8; ++w) {
            float v = rbest[w * 128 + t];
            int   i2 = ridx[w * 128 + t];
            if (v > bv || (v == bv && i2 < bi)) { bv = v; bi = i2; }
        }
        g_idx[n0 + t] = bi;
        sbi[t] = bi;
        atomicAdd(&g_cnt[bi], 1);
    }
    __syncthreads();

    // ---- fused scatter: embed sums straight out of the resident z tile ----
    {
        int r = t >> 1;
        int hf = t & 1;
        int k = sbi[r];
        float* dst = g_esum + (size_t)k * DIMV + hf * 128;
        #pragma unroll
        for (int c = 0; c < 128; ++c) {
            atomicAdd(&dst[c], zs[(hf * 128 + c) * ZS_PAD + r]);
        }
    }
}

// ---------------- kernel: EMA cluster sizes + inverse cluster scale ----------------
__global__ void k_final1(const float* __restrict__ ema_cs) {
    __shared__ float red[KCODES];
    int t = threadIdx.x;
    float ncs = 0.99f * ema_cs[t] + 0.01f * (float)g_cnt[t];
    red[t] = ncs;
    __syncthreads();
    for (int s = 512; s > 0; s >>= 1) {
        if (t < s) red[t] += red[t + s];
        __syncthreads();
    }
    float n = red[0];
    float cl = (ncs + 1e-5f) / (n + KCODES * 1e-5f) * n;
    g_invc[t] = 1.0f / cl;
}

// ---------------- kernel: updated codebook ----------------
__global__ void k_final2(const float* __restrict__ ema_es) {
    int i = blockIdx.x * blockDim.x + threadIdx.x;     // 262144
    g_newembed[i] = (0.99f * ema_es[i] + 0.01f * g_esum[i]) * g_invc[i >> 8];
}

// ---------------- kernel: gather z_q (transposed write) + loss ----------------
__global__ void k_gather(const float* __restrict__ z, float* __restrict__ out) {
    __shared__ float stg[DIMV * 33];
    __shared__ int   sk[32];
    __shared__ float warpsum[8];
    const int t = threadIdx.x;
    const int lane = t & 31;
    const int warp = t >> 5;
    const int n0 = blockIdx.x * 32;
    const int b  = n0 >> 14;
    const int s0 = n0 & (SPAT - 1);
    if (t < 32) sk[t] = g_idx[n0 + t];
    __syncthreads();
    #pragma unroll 4
    for (int i = 0; i < 32; ++i) {
        int k = sk[i];
        stg[t * 33 + i] = g_newembed[(size_t)k * DIMV + t];   // c=t, r=i
    }
    __syncthreads();
    const float* zb = z + (size_t)b * (size_t)(DIMV * SPAT) + s0;
    float*       ob = out + (size_t)b * (size_t)(DIMV * SPAT) + s0;
    float lsum = 0.0f;
    #pragma unroll 4
    for (int i = 0; i < 32; ++i) {
        int j = t + 256 * i;            // 8192: c = j>>5, r = j&31
        int c = j >> 5;
        int r = j & 31;
        float v = stg[c * 33 + r];
        size_t g = (size_t)c * CSTRIDE + r;
        float zv = zb[g];
        ob[g] = v;
        float d = zv - v;
        lsum += d * d;
    }
    #pragma unroll
    for (int o = 16; o; o >>= 1) lsum += __shfl_xor_sync(0xFFFFFFFFu, lsum, o);
    if (lane == 0) warpsum[warp] = lsum;
    __syncthreads();
    if (t == 0) {
        float s = 0.0f;
        #pragma unroll
        for (int w = 0; w < 8; ++w) s += warpsum[w];
        atomicAdd(&g_loss, s);
    }
}

// ---------------- kernel: tail outputs (loss scalar + indices as float) ----------------
__global__ void k_tail(float* __restrict__ out) {
    int i = blockIdx.x * blockDim.x + threadIdx.x;
    if (i < NQ) out[NTOT + 1 + i] = (float)g_idx[i];
    if (i == 0) out[NTOT] = 0.25f * g_loss * (1.0f / 16777216.0f);
}

// ---------------- launch ----------------
extern "C" void kernel_launch(void* const* d_in, const int* in_sizes, int n_in,
                              void* d_out, int out_size) {
    const float* z       = (const float*)d_in[0];
    const float* embed   = (const float*)d_in[1];
    const float* ema_cs  = (const float*)d_in[2];
    const float* ema_es  = (const float*)d_in[3];
    float* out = (float*)d_out;

    static bool attr_set = false;
    if (!attr_set) {
        cudaFuncSetAttribute(k_argmin, cudaFuncAttributeMaxDynamicSharedMemorySize, 179712);
        attr_set = true;
    }

    k_prep<<<1024, 256>>>(embed);
    k_argmin<<<512, 256, 179712>>>(z, embed);
    k_final1<<<1, 1024>>>(ema_cs);
    k_final2<<<1024, 256>>>(ema_es);
    k_gather<<<2048, 256>>>(z, out);
    k_tail<<<257, 256>>>(out);
}

// round 4
// speedup vs baseline: 2.6433x; 2.6433x over previous
#include <cuda_runtime.h>
#include <cuda_bf16.h>
#include <cstdint>
#include <math_constants.h>

// ---------------- problem constants ----------------
#define NQ      65536
#define DIMV    256
#define KCODES  1024
#define SPAT    16384
#define NTOT    16777216

// ---------------- device scratch ----------------
__device__ __nv_bfloat16 g_A[(size_t)NQ * 512];     // [n][0..255]=z_hi, [256..511]=z_lo
__device__ __nv_bfloat16 g_E[KCODES * 768];         // [k][0..255]=e_hi,[256..511]=e_hi,[512..767]=e_lo
__device__ float g_heq2[KCODES];
__device__ int   g_idx[NQ];
__device__ int   g_cnt[KCODES];
__device__ int   g_off[KCODES];
__device__ int   g_cur[KCODES];
__device__ int   g_rows[NQ];
__device__ float g_invc[KCODES];
__device__ float g_newembed[KCODES * DIMV];
__device__ float g_zsq;
__device__ float g_l2;

// ---------------- PTX helpers (all legal on base sm_100) ----------------
__device__ __forceinline__ uint32_t smem_u32(const void* p) {
    uint32_t a;
    asm("{ .reg .u64 t; cvta.to.shared.u64 t, %1; cvt.u32.u64 %0, t; }" : "=r"(a) : "l"(p));
    return a;
}
#define SWZ(x) ((x) ^ (((x) >> 3) & 0x70))

__device__ __forceinline__ void cpasync16(uint32_t s, const void* g) {
    asm volatile("cp.async.cg.shared.global [%0], [%1], 16;" :: "r"(s), "l"(g));
}
__device__ __forceinline__ void cpcommit() { asm volatile("cp.async.commit_group;"); }
__device__ __forceinline__ void cpwait0()  { asm volatile("cp.async.wait_group 0;" ::: "memory"); }
__device__ __forceinline__ void cpwait1()  { asm volatile("cp.async.wait_group 1;" ::: "memory"); }

__device__ __forceinline__ void ldsm4(uint32_t* r, uint32_t a) {
    asm volatile("ldmatrix.sync.aligned.m8n8.x4.shared.b16 {%0,%1,%2,%3}, [%4];"
        : "=r"(r[0]), "=r"(r[1]), "=r"(r[2]), "=r"(r[3]) : "r"(a));
}
__device__ __forceinline__ void mma16816(float* c, const uint32_t* a, uint32_t b0, uint32_t b1) {
    asm volatile("mma.sync.aligned.m16n8k16.row.col.f32.bf16.bf16.f32 "
        "{%0,%1,%2,%3}, {%4,%5,%6,%7}, {%8,%9}, {%0,%1,%2,%3};"
        : "+f"(c[0]), "+f"(c[1]), "+f"(c[2]), "+f"(c[3])
        : "r"(a[0]), "r"(a[1]), "r"(a[2]), "r"(a[3]), "r"(b0), "r"(b1));
}

// ---------------- k_prep: build E (hi|hi|lo), heq2, zero counters ----------------
__global__ void k_prep(const float* __restrict__ embed) {
    __shared__ float ws[8];
    int k = blockIdx.x, c = threadIdx.x, lane = c & 31, w = c >> 5;
    float e = embed[k * DIMV + c];
    __nv_bfloat16 hi = __float2bfloat16(e);
    __nv_bfloat16 lo = __float2bfloat16(e - __bfloat162float(hi));
    g_E[k * 768 + c]       = hi;
    g_E[k * 768 + 256 + c] = hi;
    g_E[k * 768 + 512 + c] = lo;
    float s = e * e;
    #pragma unroll
    for (int o = 16; o; o >>= 1) s += __shfl_xor_sync(0xFFFFFFFFu, s, o);
    if (lane == 0) ws[w] = s;
    __syncthreads();
    if (c == 0) {
        float t = 0;
        #pragma unroll
        for (int i = 0; i < 8; ++i) t += ws[i];
        g_heq2[k] = 0.5f * t;
        g_cnt[k] = 0;
        if (k == 0) { g_zsq = 0.0f; g_l2 = 0.0f; }
    }
}

// ---------------- k_split: transpose z -> row-major bf16 hi|lo, accumulate sum(z^2) ----------------
__global__ void k_split(const float* __restrict__ z) {
    __shared__ float tile[32][33];
    __shared__ float ws[8];
    int s0 = blockIdx.x * 32, c0 = blockIdx.y * 32, b = blockIdx.z;
    int t = threadIdx.x, lane = t & 31, w = t >> 5;
    const float* zb = z + ((size_t)b * DIMV + c0) * SPAT + s0;
    float zsq = 0.0f;
    int si = t & 31, cb = t >> 5;
    #pragma unroll
    for (int i = 0; i < 4; ++i) {
        int c = cb + 8 * i;
        float v = zb[(size_t)c * SPAT + si];
        tile[c][si] = v;
        zsq += v * v;
    }
    __syncthreads();
    int ci = t & 31, rb = t >> 5;
    #pragma unroll
    for (int i = 0; i < 4; ++i) {
        int r = rb + 8 * i;
        float v = tile[ci][r];
        __nv_bfloat16 hi = __float2bfloat16(v);
        __nv_bfloat16 lo = __float2bfloat16(v - __bfloat162float(hi));
        size_t n = (size_t)b * SPAT + s0 + r;
        g_A[n * 512 + c0 + ci] = hi;
        g_A[n * 512 + 256 + c0 + ci] = lo;
    }
    #pragma unroll
    for (int o = 16; o; o >>= 1) zsq += __shfl_xor_sync(0xFFFFFFFFu, zsq, o);
    if (lane == 0) ws[w] = zsq;
    __syncthreads();
    if (t == 0) {
        float s = 0;
        #pragma unroll
        for (int i = 0; i < 8; ++i) s += ws[i];
        atomicAdd(&g_zsq, s);
    }
}

// ---------------- k_mma: HMMA GEMM (K=768 bf16, compensated) + per-row argmin ----------------
// smem layout (relative to 1024-aligned base):
#define SM_A    0                       // 8 chunks x 16384 = 131072
#define SM_B    131072                  // 2 x 16384 = 32768
#define SM_HQ   163840                  // 4096
#define SM_RB   167936                  // 1024 (2 x 128 floats)
#define SM_RI   168960                  // 1024 (2 x 128 ints)
#define SM_END  169984
#define SM_SZ2  (SM_END + 1024)

__global__ __launch_bounds__(256, 1) void k_mma() {
    extern __shared__ char smraw[];
    uint32_t base0 = smem_u32(smraw);
    uint32_t sb = (base0 + 1023u) & ~1023u;
    char* sp = smraw + (sb - base0);
    const uint32_t A = sb + SM_A, B = sb + SM_B;
    float* heqs  = (float*)(sp + SM_HQ);
    float* rbest = (float*)(sp + SM_RB);
    int*   ridx  = (int*)(sp + SM_RI);

    const int t = threadIdx.x, lane = t & 31, w = t >> 5;
    const int warp_m = w >> 1, warp_n = w & 1;
    const int n0 = blockIdx.x * 128;

    // heq2 table
    #pragma unroll
    for (int i = 0; i < 4; ++i) heqs[t + 256 * i] = g_heq2[t + 256 * i];

    // resident A tile: 128 rows x 512 bf16 as 8 chunks [128][64], SW128-swizzled
    const __nv_bfloat16* Ag = g_A + (size_t)n0 * 512;
    #pragma unroll
    for (int j = 0; j < 32; ++j) {
        int i = t + 256 * j;            // 8192 16B segments
        int r = i >> 6, g = i & 63;
        int chunk = g >> 3, g8 = g & 7;
        cpasync16(A + chunk * 16384 + SWZ(r * 128 + g8 * 16), Ag + (size_t)r * 512 + g * 8);
    }
    cpcommit();
    // first B chunk (nt=0, kc=0) into buf 0
    {
        const __nv_bfloat16* Eg = g_E;
        #pragma unroll
        for (int j = 0; j < 4; ++j) {
            int seg = t + 256 * j;      // 1024 16B segments
            int r = seg >> 3, g8 = seg & 7;
            cpasync16(B + SWZ(r * 128 + g8 * 16), Eg + (size_t)r * 768 + g8 * 8);
        }
    }
    cpcommit();
    cpwait0();
    __syncthreads();

    float acc[2][8][4];
    float best[4];
    int   bidx[4];
    #pragma unroll
    for (int s = 0; s < 4; ++s) { best[s] = -CUDART_INF_F; bidx[s] = 0; }

    int buf = 0;
    for (int tt = 0; tt < 96; ++tt) {
        const int nt = tt / 12, kc = tt % 12;

        // prefetch next chunk into buf^1
        if (tt < 95) {
            int tn = tt + 1;
            int ntn = tn / 12, kcn = tn % 12;
            const __nv_bfloat16* Eg = g_E + (size_t)(ntn * 128) * 768 + kcn * 64;
            uint32_t bd = B + (buf ^ 1) * 16384;
            #pragma unroll
            for (int j = 0; j < 4; ++j) {
                int seg = t + 256 * j;
                int r = seg >> 3, g8 = seg & 7;
                cpasync16(bd + SWZ(r * 128 + g8 * 16), Eg + (size_t)r * 768 + g8 * 8);
            }
            cpcommit();
            cpwait1();
        } else {
            cpwait0();
        }
        __syncthreads();

        if (kc == 0) {
            #pragma unroll
            for (int mt = 0; mt < 2; ++mt)
                #pragma unroll
                for (int nti = 0; nti < 8; ++nti)
                    #pragma unroll
                    for (int q = 0; q < 4; ++q) acc[mt][nti][q] = 0.0f;
        }

        const int ac = (kc < 8) ? kc : kc - 8;   // kc>=8 reuses z_hi chunks (x e_lo)
        const uint32_t Ab = A + ac * 16384;
        const uint32_t Bb = B + buf * 16384;

        #pragma unroll
        for (int ks = 0; ks < 4; ++ks) {
            uint32_t af[2][4];
            #pragma unroll
            for (int mt = 0; mt < 2; ++mt) {
                int arow = warp_m * 32 + mt * 16 + (lane & 15);
                uint32_t off = (uint32_t)(ks * 32 + ((lane >> 4) * 16));
                ldsm4(af[mt], Ab + arow * 128 + (off ^ ((arow & 7) << 4)));
            }
            uint32_t bfg[4][4];
            #pragma unroll
            for (int ntp = 0; ntp < 4; ++ntp) {
                int sel = lane >> 3;             // 0..3: (tile, khalf)
                int brow = warp_n * 64 + ntp * 16 + (sel >> 1) * 8 + (lane & 7);
                uint32_t off = (uint32_t)(ks * 32 + (sel & 1) * 16);
                ldsm4(bfg[ntp], Bb + brow * 128 + (off ^ ((brow & 7) << 4)));
            }
            #pragma unroll
            for (int mt = 0; mt < 2; ++mt)
                #pragma unroll
                for (int nti = 0; nti < 8; ++nti) {
                    int ntp = nti >> 1, pr = (nti & 1) * 2;
                    mma16816(acc[mt][nti], af[mt], bfg[ntp][pr], bfg[ntp][pr + 1]);
                }
        }

        // per-N-tile epilogue: fold 0.5|e|^2, running per-thread argmax
        if (kc == 11) {
            #pragma unroll
            for (int mt = 0; mt < 2; ++mt)
                #pragma unroll
                for (int nti = 0; nti < 8; ++nti) {
                    int code0 = nt * 128 + warp_n * 64 + nti * 8 + 2 * (lane & 3);
                    float h0 = heqs[code0], h1 = heqs[code0 + 1];
                    float v;
                    v = acc[mt][nti][0] - h0;
                    if (v > best[2 * mt]) { best[2 * mt] = v; bidx[2 * mt] = code0; }
                    v = acc[mt][nti][1] - h1;
                    if (v > best[2 * mt]) { best[2 * mt] = v; bidx[2 * mt] = code0 + 1; }
                    v = acc[mt][nti][2] - h0;
                    if (v > best[2 * mt + 1]) { best[2 * mt + 1] = v; bidx[2 * mt + 1] = code0; }
                    v = acc[mt][nti][3] - h1;
                    if (v > best[2 * mt + 1]) { best[2 * mt + 1] = v; bidx[2 * mt + 1] = code0 + 1; }
                }
        }
        __syncthreads();
        buf ^= 1;
    }

    // cross-lane (4-lane row group) reduction, tie -> smaller index
    #pragma unroll
    for (int s = 0; s < 4; ++s) {
        #pragma unroll
        for (int o = 1; o <= 2; o <<= 1) {
            float ov = __shfl_xor_sync(0xFFFFFFFFu, best[s], o);
            int   oi = __shfl_xor_sync(0xFFFFFFFFu, bidx[s], o);
            if (ov > best[s] || (ov == best[s] && oi < bidx[s])) { best[s] = ov; bidx[s] = oi; }
        }
    }
    if ((lane & 3) == 0) {
        int g = lane >> 2;
        #pragma unroll
        for (int s = 0; s < 4; ++s) {
            int row = warp_m * 32 + (s >> 1) * 16 + (s & 1) * 8 + g;
            rbest[warp_n * 128 + row] = best[s];
            ridx[warp_n * 128 + row]  = bidx[s];
        }
    }
    __syncthreads();
    if (t < 128) {
        float v0 = rbest[t], v1 = rbest[128 + t];
        int   i0 = ridx[t],  i1 = ridx[128 + t];
        int bi = (v1 > v0 || (v1 == v0 && i1 < i0)) ? i1 : i0;
        g_idx[n0 + t] = bi;
        atomicAdd(&g_cnt[bi], 1);
    }
}

// ---------------- k_scan: EMA sizes + invc + exclusive prefix of counts ----------------
__global__ void k_scan(const float* __restrict__ ema_cs) {
    __shared__ float red[KCODES];
    __shared__ int sc[KCODES];
    int t = threadIdx.x;
    int c = g_cnt[t];
    float ncs = 0.99f * ema_cs[t] + 0.01f * (float)c;
    red[t] = ncs; sc[t] = c;
    __syncthreads();
    for (int s = 512; s > 0; s >>= 1) { if (t < s) red[t] += red[t + s]; __syncthreads(); }
    float n = red[0];
    for (int off = 1; off < KCODES; off <<= 1) {
        int v = (t >= off) ? sc[t - off] : 0;
        __syncthreads();
        sc[t] += v;
        __syncthreads();
    }
    int excl = sc[t] - c;
    g_off[t] = excl; g_cur[t] = excl;
    float cl = (ncs + 1e-5f) / (n + KCODES * 1e-5f) * n;
    g_invc[t] = 1.0f / cl;
}

// ---------------- k_bucket: scatter row ids into code buckets ----------------
__global__ void k_bucket() {
    int n = blockIdx.x * 256 + threadIdx.x;
    int k = g_idx[n];
    int p = atomicAdd(&g_cur[k], 1);
    g_rows[p] = n;
}

// ---------------- k_esum: per-code sum + new codebook + loss terms ----------------
__global__ void k_esum(const float* __restrict__ ema_es) {
    __shared__ float ws[8];
    int k = blockIdx.x, c = threadIdx.x, lane = c & 31, w = c >> 5;
    int off = g_off[k], cnt = g_cnt[k];
    float acc = 0.0f;
    for (int i = 0; i < cnt; ++i) {
        int n = g_rows[off + i];
        const __nv_bfloat16* row = g_A + (size_t)n * 512;
        acc += __bfloat162float(row[c]) + __bfloat162float(row[256 + c]);
    }
    float newe = (0.99f * ema_es[k * DIMV + c] + 0.01f * acc) * g_invc[k];
    g_newembed[k * DIMV + c] = newe;
    float part = (float)cnt * newe * newe - 2.0f * acc * newe;
    #pragma unroll
    for (int o = 16; o; o >>= 1) part += __shfl_xor_sync(0xFFFFFFFFu, part, o);
    if (lane == 0) ws[w] = part;
    __syncthreads();
    if (c == 0) {
        float s = 0;
        #pragma unroll
        for (int i = 0; i < 8; ++i) s += ws[i];
        atomicAdd(&g_l2, s);
    }
}

// ---------------- k_gather: write z_q (transposed), indices, loss ----------------
__global__ void k_gather(float* __restrict__ out) {
    __shared__ float stg[DIMV * 33];
    __shared__ int sk[32];
    int t = threadIdx.x;
    int n0 = blockIdx.x * 32;
    int b = n0 >> 14, s0 = n0 & (SPAT - 1);
    if (t < 32) {
        int k = g_idx[n0 + t];
        sk[t] = k;
        out[NTOT + 1 + n0 + t] = (float)k;
    }
    __syncthreads();
    #pragma unroll 4
    for (int i = 0; i < 32; ++i)
        stg[t * 33 + i] = g_newembed[sk[i] * DIMV + t];
    __syncthreads();
    float* ob = out + (size_t)b * (DIMV * SPAT) + s0;
    #pragma unroll 4
    for (int i = 0; i < 32; ++i) {
        int j = t + 256 * i;
        int c = j >> 5, r = j & 31;
        ob[(size_t)c * SPAT + r] = stg[c * 33 + r];
    }
    if (blockIdx.x == 0 && t == 0)
        out[NTOT] = 0.25f * (g_zsq + g_l2) * (1.0f / 16777216.0f);
}

// ---------------- launch ----------------
extern "C" void kernel_launch(void* const* d_in, const int* in_sizes, int n_in,
                              void* d_out, int out_size) {
    const float* z      = (const float*)d_in[0];
    const float* embed  = (const float*)d_in[1];
    const float* ema_cs = (const float*)d_in[2];
    const float* ema_es = (const float*)d_in[3];
    float* out = (float*)d_out;

    static bool init = false;
    if (!init) {
        cudaFuncSetAttribute(k_mma, cudaFuncAttributeMaxDynamicSharedMemorySize, SM_SZ2);
        init = true;
    }

    k_prep<<<KCODES, 256>>>(embed);
    k_split<<<dim3(512, 8, 4), 256>>>(z);
    k_mma<<<512, 256, SM_SZ2>>>();
    k_scan<<<1, 1024>>>(ema_cs);
    k_bucket<<<256, 256>>>();
    k_esum<<<KCODES, 256>>>(ema_es);
    k_gather<<<2048, 256>>>(out);
}